// round 7
// baseline (speedup 1.0000x reference)
#include <cuda_runtime.h>
#include <cuda_fp16.h>
#include <cstdint>

// ---------------------------------------------------------------------------
// out[b,o,hw] = sum_c W[o,c] * relu(x[b,c,hw]*scale[c]+shift[c])
// Single-pass GEMM per batch: M=o(192), N=hw(49,pad 64), K=c(2112).
//  A = W16[o][c] (k-major, cp.async 5-stage ring, L2-resident)
//  B = x tile [32c][49hw]: contiguous float4 LDG -> BN+ReLU+cvt fp16 -> STS
//      [c][hw] smem; fragments via ldmatrix.x4.trans (B col-major frags).
// ---------------------------------------------------------------------------
constexpr int CIN   = 2112;
constexpr int COUT  = 192;
constexpr int HWSZ  = 49;
constexpr int BATCH = 256;
constexpr int BK    = 32;
constexpr int NKT   = CIN / BK;        // 66

constexpr int A_STRIDE = 80;                   // 32 halves + 8 pad
constexpr int A_STAGE  = COUT * A_STRIDE;      // 15360
constexpr int NSTA     = 5;
constexpr int B_STRIDE = 144;                  // 64 halves + 8 pad (16B-period-8: ldsm clean)
constexpr int B_STAGE  = BK * B_STRIDE;        // 4608
constexpr int NSTB     = 3;
constexpr int SMEM_A   = 0;
constexpr int SMEM_B   = NSTA * A_STAGE;       // 76800
constexpr int SMEM_TOTAL = SMEM_B + NSTB * B_STAGE;  // 90624

__device__ __align__(16) __half  g_W16[COUT * CIN];
__device__ __align__(16) float2  g_ss[CIN];    // {scale, shift}

__device__ __forceinline__ uint32_t smem_u32(const void* p) {
    uint32_t a;
    asm("{ .reg .u64 t; cvta.to.shared.u64 t, %1; cvt.u32.u64 %0, t; }" : "=r"(a) : "l"(p));
    return a;
}
__device__ __forceinline__ void cp_async16(uint32_t saddr, const void* g) {
    asm volatile("cp.async.cg.shared.global [%0], [%1], 16;" :: "r"(saddr), "l"(g));
}
__device__ __forceinline__ void cp_commit() { asm volatile("cp.async.commit_group;"); }
__device__ __forceinline__ void cp_wait3()  { asm volatile("cp.async.wait_group 3;"); }
__device__ __forceinline__ void ldsm_x4(uint32_t* r, uint32_t addr) {
    asm volatile("ldmatrix.sync.aligned.m8n8.x4.shared.b16 {%0,%1,%2,%3}, [%4];"
                 : "=r"(r[0]), "=r"(r[1]), "=r"(r[2]), "=r"(r[3]) : "r"(addr));
}
__device__ __forceinline__ void ldsm_x4t(uint32_t* r, uint32_t addr) {
    asm volatile("ldmatrix.sync.aligned.m8n8.x4.trans.shared.b16 {%0,%1,%2,%3}, [%4];"
                 : "=r"(r[0]), "=r"(r[1]), "=r"(r[2]), "=r"(r[3]) : "r"(addr));
}
__device__ __forceinline__ void mma16816(float& c0, float& c1, float& c2, float& c3,
                                         uint32_t a0, uint32_t a1, uint32_t a2, uint32_t a3,
                                         uint32_t b0, uint32_t b1) {
    asm volatile(
        "mma.sync.aligned.m16n8k16.row.col.f32.f16.f16.f32 "
        "{%0,%1,%2,%3}, {%4,%5,%6,%7}, {%8,%9}, {%0,%1,%2,%3};"
        : "+f"(c0), "+f"(c1), "+f"(c2), "+f"(c3)
        : "r"(a0), "r"(a1), "r"(a2), "r"(a3), "r"(b0), "r"(b1));
}

// ---------------------------------------------------------------------------
// prep: W -> fp16 (blocks 0..197), BN coeffs (blocks 198..206)
// ---------------------------------------------------------------------------
constexpr int NW_BLK = (COUT * CIN) / 2048;   // 198
__global__ void prep_kernel(const float* __restrict__ W,
                            const float* __restrict__ gamma, const float* __restrict__ beta,
                            const float* __restrict__ mean,  const float* __restrict__ var) {
    const int tid = threadIdx.x, bid = blockIdx.x;
    if (bid < NW_BLK) {
        const int base4 = bid * 512 + tid;
#pragma unroll
        for (int i = 0; i < 2; i++) {
            const int i4 = base4 + 256 * i;
            float4 f = *reinterpret_cast<const float4*>(W + (size_t)i4 * 4);
            __half2 lo = __floats2half2_rn(f.x, f.y);
            __half2 hi = __floats2half2_rn(f.z, f.w);
            uint2 u = {*reinterpret_cast<uint32_t*>(&lo), *reinterpret_cast<uint32_t*>(&hi)};
            *reinterpret_cast<uint2*>(g_W16 + (size_t)i4 * 4) = u;
        }
    } else {
        const int c = (bid - NW_BLK) * 256 + tid;
        if (c < CIN) {
            float inv = rsqrtf(var[c] + 1e-5f);
            float s = gamma[c] * inv;
            g_ss[c] = make_float2(s, fmaf(-mean[c], s, beta[c]));
        }
    }
}

// ---------------------------------------------------------------------------
// GEMM: grid = 256 (one CTA per batch), 128 threads = 4 warps (48 o-rows each).
// ---------------------------------------------------------------------------
__global__ void __launch_bounds__(128, 2)
gemm_kernel(const float* __restrict__ x, float* __restrict__ out) {
    extern __shared__ char smem[];
    const uint32_t sb = smem_u32(smem);
    const int tid = threadIdx.x;
    const int l = tid & 31;
    const int w = tid >> 5;
    const int b = blockIdx.x;

    // zero B region (pads must be 0; data cols rewritten each iter)
#pragma unroll
    for (int i = 0; i < 7; i++) {
        const int idx = tid + 128 * i;
        if (idx < NSTB * B_STAGE / 16)
            reinterpret_cast<uint4*>(smem + SMEM_B)[idx] = make_uint4(0, 0, 0, 0);
    }

    // x tile base: (b*2112 + kt*32)*49 floats — always 16B aligned
    const float4* xb4 = reinterpret_cast<const float4*>(x + (size_t)b * CIN * HWSZ);

    auto cpA = [&](int kt, int st) {
        const uint32_t as = sb + SMEM_A + st * A_STAGE;
        const __half* src = g_W16 + kt * BK;
#pragma unroll
        for (int i = 0; i < 6; i++) {
            const int idx = tid + 128 * i;
            const int row = idx >> 2, j = idx & 3;
            cp_async16(as + row * A_STRIDE + j * 16, src + (size_t)row * CIN + j * 8);
        }
    };

    float4 rb[2][4];
    auto ldgB = [&](int kt, float4* r) {
        const float4* p = xb4 + kt * 392;      // 392 float4 = 32*49 floats
        r[0] = p[tid]; r[1] = p[tid + 128]; r[2] = p[tid + 256];
        if (tid < 8) r[3] = p[tid + 384];
    };
    auto stsB = [&](int kt, const float4* r, int st) {
        char* bs = smem + SMEM_B + st * B_STAGE;
        const float2* ss = g_ss + kt * BK;
#pragma unroll
        for (int q = 0; q < 4; q++) {
            if (q == 3 && tid >= 8) continue;
            const int i4 = (q < 3) ? tid + 128 * q : 384 + tid;
            const int idx0 = i4 * 4;
            const int cf = (idx0 * 1338) >> 16;
            const int cl = ((idx0 + 3) * 1338) >> 16;
            const float2 s0 = ss[cf], s1 = ss[cl];
            const float v[4] = {r[q].x, r[q].y, r[q].z, r[q].w};
#pragma unroll
            for (int e = 0; e < 4; e++) {
                const int idx = idx0 + e;
                const int c = (idx * 1338) >> 16;
                const int hw = idx - 49 * c;
                const float2 sc = (c == cf) ? s0 : s1;
                const float t = fmaxf(fmaf(v[e], sc.x, sc.y), 0.0f);
                *reinterpret_cast<__half*>(bs + c * B_STRIDE + hw * 2) = __float2half_rn(t);
            }
        }
    };

    // fragment lane addressing
    const uint32_t aLane = (uint32_t)((48 * w + (l & 15)) * A_STRIDE + (l >> 4) * 16);
    const uint32_t bLane = (uint32_t)(((l & 7) + ((l >> 3) & 1) * 8) * B_STRIDE + (l >> 4) * 16);

    float acc[3][7][4];
#pragma unroll
    for (int mt = 0; mt < 3; mt++)
#pragma unroll
        for (int nt = 0; nt < 7; nt++)
#pragma unroll
            for (int c = 0; c < 4; c++) acc[mt][nt][c] = 0.0f;

    // prologue
    cpA(0, 0); cp_commit();
    cpA(1, 1); cp_commit();
    cpA(2, 2); cp_commit();
    ldgB(0, rb[0]);
    ldgB(1, rb[1]);
    __syncthreads();               // zero-fill published before stsB
    stsB(0, rb[0], 0);

    int sAr = 0, sAw = 3, sBr = 0, sBw = 1;
#pragma unroll 1
    for (int kt = 0; kt < NKT; kt++) {
        if (kt + 3 < NKT) cpA(kt + 3, sAw);     // stage last consumed at kt-2: safe
        cp_commit();
        if (kt + 2 < NKT) ldgB(kt + 2, rb[kt & 1]);
        if (kt + 1 < NKT) stsB(kt + 1, rb[(kt + 1) & 1], sBw);  // stage last used kt-2
        cp_wait3();
        __syncthreads();           // publishes A stage kt + B stage kt

        const uint32_t sA = sb + SMEM_A + sAr * A_STAGE;
        const uint32_t sB = sb + SMEM_B + sBr * B_STAGE;
#pragma unroll
        for (int s = 0; s < 2; s++) {
            uint32_t af[3][4], bf[4][4];
#pragma unroll
            for (int mt = 0; mt < 3; mt++)
                ldsm_x4(af[mt], sA + aLane + mt * 16 * A_STRIDE + s * 32);
#pragma unroll
            for (int nc = 0; nc < 4; nc++)
                ldsm_x4t(bf[nc], sB + bLane + s * 16 * B_STRIDE + nc * 32);
#pragma unroll
            for (int mt = 0; mt < 3; mt++) {
#pragma unroll
                for (int nc = 0; nc < 4; nc++) {
                    mma16816(acc[mt][2 * nc][0], acc[mt][2 * nc][1],
                             acc[mt][2 * nc][2], acc[mt][2 * nc][3],
                             af[mt][0], af[mt][1], af[mt][2], af[mt][3],
                             bf[nc][0], bf[nc][1]);
                    if (nc < 3)
                        mma16816(acc[mt][2 * nc + 1][0], acc[mt][2 * nc + 1][1],
                                 acc[mt][2 * nc + 1][2], acc[mt][2 * nc + 1][3],
                                 af[mt][0], af[mt][1], af[mt][2], af[mt][3],
                                 bf[nc][2], bf[nc][3]);
                }
            }
        }
        sAr = (sAr + 1 == NSTA) ? 0 : sAr + 1;
        sAw = (sAw + 1 == NSTA) ? 0 : sAw + 1;
        sBr = (sBr + 1 == NSTB) ? 0 : sBr + 1;
        sBw = (sBw + 1 == NSTB) ? 0 : sBw + 1;
    }

    // epilogue: lane l, m-row = l>>2 (+8 for c2,c3), n = 2*(l&3)+{0,1} (+8*nt)
    const int t4 = l & 3;
    float* ob = out + (size_t)b * COUT * HWSZ;
#pragma unroll
    for (int mt = 0; mt < 3; mt++) {
#pragma unroll
        for (int h = 0; h < 2; h++) {
            const int o = 48 * w + 16 * mt + (l >> 2) + 8 * h;
            float* op = ob + o * HWSZ;
#pragma unroll
            for (int nt = 0; nt < 7; nt++) {
                const int n = 8 * nt + 2 * t4;
                if (nt < 6) {
                    op[n]     = acc[mt][nt][2 * h + 0];
                    op[n + 1] = acc[mt][nt][2 * h + 1];
                } else if (t4 == 0) {
                    op[48] = acc[mt][6][2 * h + 0];   // n=48 only; n=49.. padded away
                }
            }
        }
    }
}

// ---------------------------------------------------------------------------
extern "C" void kernel_launch(void* const* d_in, const int* in_sizes, int n_in,
                              void* d_out, int out_size) {
    (void)in_sizes; (void)n_in; (void)out_size;
    const float* x     = (const float*)d_in[0];
    const float* gamma = (const float*)d_in[1];
    const float* beta  = (const float*)d_in[2];
    const float* rmean = (const float*)d_in[3];
    const float* rvar  = (const float*)d_in[4];
    const float* W     = (const float*)d_in[5];
    float* out = (float*)d_out;

    cudaFuncSetAttribute(gemm_kernel, cudaFuncAttributeMaxDynamicSharedMemorySize, SMEM_TOTAL);

    prep_kernel<<<NW_BLK + (CIN + 255) / 256, 256>>>(W, gamma, beta, rmean, rvar);
    gemm_kernel<<<BATCH, 128, SMEM_TOTAL>>>(x, out);
}

// round 8
// speedup vs baseline: 1.9242x; 1.9242x over previous
#include <cuda_runtime.h>
#include <cuda_fp16.h>
#include <cstdint>

// ---------------------------------------------------------------------------
// out[b,o,hw] = sum_c W[o,c] * relu(x[b,c,hw]*scale[c]+shift[c])
// Pass 1 (fuse): h[m,k] = fp16(relu(BN(x))), m=b*49+hw, k=c; W -> fp16.
// Pass 2 (gemm): fp16 mma.sync m16n8k16; grid (196,2), BM=64 BN=96 BK=64,
//   3-stage cp.async ring, ONE barrier/iter, register-double-buffered ldsm.
// ---------------------------------------------------------------------------
constexpr int CIN   = 2112;
constexpr int COUT  = 192;
constexpr int HWSZ  = 49;
constexpr int M_TOTAL = 256 * HWSZ;   // 12544
constexpr int BM = 64;
constexpr int BN = 96;
constexpr int BK = 64;
constexpr int NKT = CIN / BK;         // 33
constexpr int GRID_M = M_TOTAL / BM;  // 196

constexpr int STRIDE  = 144;                     // 64 halves + 8 pad
constexpr int A_STAGE = BM * STRIDE;             // 9216
constexpr int B_STAGE = BN * STRIDE;             // 13824
constexpr int SMEM_B0 = 3 * A_STAGE;             // 27648
constexpr int SMEM_TOTAL = SMEM_B0 + 3 * B_STAGE;  // 69120

__device__ __align__(16) __half g_h16[(size_t)M_TOTAL * CIN];
__device__ __align__(16) __half g_W16[COUT * CIN];

constexpr int CCH = 64;
constexpr int NCH = CIN / CCH;            // 33
constexpr int NT_CTA = 256 * NCH;         // 8448
constexpr int NW_CTA = (COUT * CIN) / 2048;  // 198

__device__ __forceinline__ uint32_t smem_u32(const void* p) {
    uint32_t a;
    asm("{ .reg .u64 t; cvta.to.shared.u64 t, %1; cvt.u32.u64 %0, t; }" : "=r"(a) : "l"(p));
    return a;
}
__device__ __forceinline__ uint32_t pack_h2(float lo, float hi) {
    __half2 h = __floats2half2_rn(lo, hi);
    return *reinterpret_cast<uint32_t*>(&h);
}
__device__ __forceinline__ void cp_async16(uint32_t saddr, const void* g) {
    asm volatile("cp.async.cg.shared.global [%0], [%1], 16;" :: "r"(saddr), "l"(g));
}
__device__ __forceinline__ void cp_commit() { asm volatile("cp.async.commit_group;"); }
__device__ __forceinline__ void cp_wait1()  { asm volatile("cp.async.wait_group 1;"); }
__device__ __forceinline__ void ldsm_x4(uint32_t* r, uint32_t addr) {
    asm volatile("ldmatrix.sync.aligned.m8n8.x4.shared.b16 {%0,%1,%2,%3}, [%4];"
                 : "=r"(r[0]), "=r"(r[1]), "=r"(r[2]), "=r"(r[3]) : "r"(addr));
}
__device__ __forceinline__ void mma16816(float& c0, float& c1, float& c2, float& c3,
                                         uint32_t a0, uint32_t a1, uint32_t a2, uint32_t a3,
                                         uint32_t b0, uint32_t b1) {
    asm volatile(
        "mma.sync.aligned.m16n8k16.row.col.f32.f16.f16.f32 "
        "{%0,%1,%2,%3}, {%4,%5,%6,%7}, {%8,%9}, {%0,%1,%2,%3};"
        : "+f"(c0), "+f"(c1), "+f"(c2), "+f"(c3)
        : "r"(a0), "r"(a1), "r"(a2), "r"(a3), "r"(b0), "r"(b1));
}

// ---------------------------------------------------------------------------
// Pass 1: BN+ReLU+fp16 transpose of x (vectorized) + W -> fp16
// ---------------------------------------------------------------------------
__global__ void __launch_bounds__(256)
fuse_kernel(const float* __restrict__ x,
            const float* __restrict__ gamma, const float* __restrict__ beta,
            const float* __restrict__ mean,  const float* __restrict__ var,
            const float* __restrict__ W) {
    const int tid = threadIdx.x;
    const int bid = blockIdx.x;

    if (bid >= NT_CTA) {   // W conversion: 512 float4 per CTA
        const int base4 = (bid - NT_CTA) * 512 + tid;
#pragma unroll
        for (int i = 0; i < 2; i++) {
            const int i4 = base4 + 256 * i;
            float4 f = *reinterpret_cast<const float4*>(W + (size_t)i4 * 4);
            uint2 u;
            u.x = pack_h2(f.x, f.y);
            u.y = pack_h2(f.z, f.w);
            *reinterpret_cast<uint2*>(g_W16 + (size_t)i4 * 4) = u;
        }
        return;
    }

    __shared__ float smf[CCH * 51];      // [c][hw], row stride 51
    __shared__ float ssc[CCH], ssh[CCH];

    const int b  = bid / NCH;
    const int c0 = (bid - b * NCH) * CCH;

    if (tid < CCH) {
        const int c = c0 + tid;
        float inv = rsqrtf(var[c] + 1e-5f);
        float s = gamma[c] * inv;
        ssc[tid] = s;
        ssh[tid] = fmaf(-mean[c], s, beta[c]);
    }
    __syncthreads();

    const float* src = x + ((size_t)b * CIN + c0) * HWSZ;
#pragma unroll
    for (int i = 0; i < 4; i++) {
        const int i4 = tid + 256 * i;
        if (i4 < 784) {
            float4 f = *reinterpret_cast<const float4*>(src + i4 * 4);
            const float vv[4] = {f.x, f.y, f.z, f.w};
#pragma unroll
            for (int e = 0; e < 4; e++) {
                const int idx = i4 * 4 + e;               // c*49 + hw
                const int c = (unsigned)idx / HWSZ;
                smf[idx + 2 * c] = fmaxf(fmaf(vv[e], ssc[c], ssh[c]), 0.0f);
            }
        }
    }
    __syncthreads();

#pragma unroll
    for (int i = 0; i < 4; i++) {
        const int j = tid + 256 * i;
        if (j < HWSZ * 16) {
            const int hw = j >> 4, cq = j & 15;
            const float v0 = smf[(4 * cq + 0) * 51 + hw];
            const float v1 = smf[(4 * cq + 1) * 51 + hw];
            const float v2 = smf[(4 * cq + 2) * 51 + hw];
            const float v3 = smf[(4 * cq + 3) * 51 + hw];
            uint2 u;
            u.x = pack_h2(v0, v1);
            u.y = pack_h2(v2, v3);
            *reinterpret_cast<uint2*>(g_h16 + (size_t)(b * HWSZ + hw) * CIN + c0 + 4 * cq) = u;
        }
    }
}

// ---------------------------------------------------------------------------
// Pass 2: GEMM. grid (196, 2); 128 threads = 2(M) x 2(N) warps, warp 32x48.
// ---------------------------------------------------------------------------
__global__ void __launch_bounds__(128, 2)
gemm_kernel(float* __restrict__ out) {
    extern __shared__ char smem[];
    const uint32_t sb = smem_u32(smem);
    const int tid = threadIdx.x;
    const int l = tid & 31;
    const int w = tid >> 5;
    const int m0 = blockIdx.x * BM;
    const int n0 = blockIdx.y * BN;

    const int g = l >> 2, t4 = l & 3;
    const int wm = (w >> 1) * 32;
    const int wn = (w & 1) * 48;
    // A frag: r0=[m0-7,k0-7] r1=[m8-15,k0-7] r2=[m0-7,k8-15] r3=[m8-15,k8-15]
    const int rAf = (l & 7) + (((l >> 3) & 1) << 3);
    const int cAf = (l >> 4) * 16;
    const uint32_t aFragBase = (uint32_t)((wm + rAf) * STRIDE + cAf);
    // B frag: r0=[n0-7,k0-7] r1=[n0-7,k8-15] r2=[n8-15,k0-7] r3=[n8-15,k8-15]
    const int rBf = (l & 7) + ((l >> 4) << 3);
    const int cBf = ((l >> 3) & 1) * 16;
    const uint32_t bFragBase = (uint32_t)((wn + rBf) * STRIDE + cBf);

    float acc[2][6][4];
#pragma unroll
    for (int mt = 0; mt < 2; mt++)
#pragma unroll
        for (int nt = 0; nt < 6; nt++)
#pragma unroll
            for (int c = 0; c < 4; c++) acc[mt][nt][c] = 0.0f;

    // cp.async: A 64 rows x 8 chunks = 512 (4/thread), B 96 x 8 = 768 (6/thread)
    auto cp_tile = [&](int kt) {
        const int stg = kt % 3;
        const uint32_t as = sb + stg * A_STAGE;
        const uint32_t bs = sb + SMEM_B0 + stg * B_STAGE;
        const __half* ah = g_h16 + (size_t)m0 * CIN + kt * BK;
#pragma unroll
        for (int i = 0; i < 4; i++) {
            const int idx = tid + 128 * i;
            const int row = idx >> 3, j = idx & 7;
            cp_async16(as + row * STRIDE + j * 16, ah + (size_t)row * CIN + j * 8);
        }
        const __half* bh = g_W16 + (size_t)n0 * CIN + kt * BK;
#pragma unroll
        for (int i = 0; i < 6; i++) {
            const int idx = tid + 128 * i;
            const int row = idx >> 3, j = idx & 7;
            cp_async16(bs + row * STRIDE + j * 16, bh + (size_t)row * CIN + j * 8);
        }
    };

    uint32_t af[2][2][4], bf[2][3][4];
    auto ldfrags = [&](uint32_t sA, uint32_t sB, int s, int buf) {
#pragma unroll
        for (int mt = 0; mt < 2; mt++)
            ldsm_x4(af[buf][mt], sA + aFragBase + mt * 16 * STRIDE + s * 32);
#pragma unroll
        for (int p = 0; p < 3; p++)
            ldsm_x4(bf[buf][p], sB + bFragBase + p * 16 * STRIDE + s * 32);
    };

    // prologue: 2 tiles in flight
    cp_tile(0); cp_commit();
    cp_tile(1); cp_commit();

#pragma unroll 1
    for (int kt = 0; kt < NKT; kt++) {
        cp_wait1();              // group kt complete (pending stays at 2: always-commit)
        __syncthreads();         // publish stage kt; license overwrite of (kt-1)%3
        if (kt + 2 < NKT) cp_tile(kt + 2);
        cp_commit();             // commit every iter (possibly empty group)

        const uint32_t sA = sb + (kt % 3) * A_STAGE;
        const uint32_t sB = sb + SMEM_B0 + (kt % 3) * B_STAGE;
        ldfrags(sA, sB, 0, 0);
#pragma unroll
        for (int s = 0; s < 4; s++) {       // 4 k16-steps per BK=64
            if (s < 3) ldfrags(sA, sB, s + 1, (s + 1) & 1);
            const int cb = s & 1;
#pragma unroll
            for (int mt = 0; mt < 2; mt++)
#pragma unroll
                for (int p = 0; p < 3; p++) {
                    mma16816(acc[mt][2 * p][0], acc[mt][2 * p][1],
                             acc[mt][2 * p][2], acc[mt][2 * p][3],
                             af[cb][mt][0], af[cb][mt][1], af[cb][mt][2], af[cb][mt][3],
                             bf[cb][p][0], bf[cb][p][1]);
                    mma16816(acc[mt][2 * p + 1][0], acc[mt][2 * p + 1][1],
                             acc[mt][2 * p + 1][2], acc[mt][2 * p + 1][3],
                             af[cb][mt][0], af[cb][mt][1], af[cb][mt][2], af[cb][mt][3],
                             bf[cb][p][2], bf[cb][p][3]);
                }
        }
    }

    // epilogue
#pragma unroll
    for (int mt = 0; mt < 2; mt++) {
#pragma unroll
        for (int h = 0; h < 2; h++) {
            const int m = m0 + wm + mt * 16 + g + 8 * h;
            const int b = m / HWSZ, hw = m - b * HWSZ;
            float* op = out + (size_t)b * (COUT * HWSZ) + hw;
#pragma unroll
            for (int nt = 0; nt < 6; nt++) {
                const int n = n0 + wn + nt * 8 + 2 * t4;
                op[(size_t)n * HWSZ]       = acc[mt][nt][2 * h + 0];
                op[(size_t)(n + 1) * HWSZ] = acc[mt][nt][2 * h + 1];
            }
        }
    }
}

// ---------------------------------------------------------------------------
extern "C" void kernel_launch(void* const* d_in, const int* in_sizes, int n_in,
                              void* d_out, int out_size) {
    (void)in_sizes; (void)n_in; (void)out_size;
    const float* x     = (const float*)d_in[0];
    const float* gamma = (const float*)d_in[1];
    const float* beta  = (const float*)d_in[2];
    const float* rmean = (const float*)d_in[3];
    const float* rvar  = (const float*)d_in[4];
    const float* W     = (const float*)d_in[5];
    float* out = (float*)d_out;

    cudaFuncSetAttribute(gemm_kernel, cudaFuncAttributeMaxDynamicSharedMemorySize, SMEM_TOTAL);
    cudaFuncSetAttribute(gemm_kernel, cudaFuncAttributePreferredSharedMemoryCarveout, 100);

    fuse_kernel<<<NT_CTA + NW_CTA, 256>>>(x, gamma, beta, rmean, rvar, W);
    dim3 grid(GRID_M, 2);
    gemm_kernel<<<grid, 128, SMEM_TOTAL>>>(out);
}